// round 3
// baseline (speedup 1.0000x reference)
#include <cuda_runtime.h>
#include <math.h>
#include <stdint.h>

#define Bsz 4
#define Tq  128
#define Dm  256
#define FFd 1024
#define NHa 8
#define VOC 32000
#define MDm 128
#define MHh 4
#define HDm 32
#define SLT 512
#define CD  384
#define IFW 516   // MH*(4*HD+1)

// ---------------- device scratch ----------------
__device__ float g_x[512 * 256];
__device__ float g_h[512 * 256];
__device__ float g_qkv[512 * 768];
__device__ float g_o[512 * 256];
__device__ float g_ff[512 * 1024];
__device__ float g_A[512 * 384];
__device__ float g_ifh[512 * 516];
__device__ float g_rvh[4 * 129 * 128];
__device__ int   g_flags[16];

// ---------------- helpers ----------------
__device__ __forceinline__ float geluf(float v) {
    float c = v + 0.044715f * v * v * v;
    return 0.5f * v * (1.f + tanhf(0.7978845608028654f * c));
}
__device__ __forceinline__ float sigmoidf_(float x) { return 1.f / (1.f + expf(-x)); }

// ---------------- embedding ----------------
__global__ __launch_bounds__(256) void embed_k(const int* __restrict__ ids,
                                               const float* __restrict__ tok,
                                               const float* __restrict__ pos,
                                               float* __restrict__ x) {
    int i = blockIdx.x * 256 + threadIdx.x;  // 131072
    int d = i & 255, bt = i >> 8, t = bt & 127;
    x[i] = tok[ids[bt] * 256 + d] + pos[t * 256 + d];
}

// ---------------- layernorm (1 warp per row of 256) ----------------
__global__ __launch_bounds__(256) void ln_k(const float* __restrict__ x,
                                            const float* __restrict__ g,
                                            const float* __restrict__ b,
                                            float* __restrict__ o, int ldc) {
    int row = blockIdx.x * 8 + (threadIdx.x >> 5);
    int lane = threadIdx.x & 31;
    const float* xr = x + row * 256;
    float v[8];
    float s = 0.f;
#pragma unroll
    for (int i = 0; i < 8; i++) { v[i] = xr[lane + 32 * i]; s += v[i]; }
#pragma unroll
    for (int of = 16; of; of >>= 1) s += __shfl_xor_sync(0xffffffffu, s, of);
    float m = s * (1.f / 256.f);
    float q = 0.f;
#pragma unroll
    for (int i = 0; i < 8; i++) { float d = v[i] - m; q += d * d; }
#pragma unroll
    for (int of = 16; of; of >>= 1) q += __shfl_xor_sync(0xffffffffu, q, of);
    float inv = rsqrtf(q * (1.f / 256.f) + 1e-5f);
#pragma unroll
    for (int i = 0; i < 8; i++) {
        int c = lane + 32 * i;
        o[row * ldc + c] = (v[i] - m) * inv * g[c] + b[c];
    }
}

// ---------------- attention: CTA per (b, head) ----------------
__global__ __launch_bounds__(128) void attn_k(const float* __restrict__ qkv,
                                              float* __restrict__ o) {
    int b = blockIdx.x >> 3, h = blockIdx.x & 7;
    __shared__ float ks[128 * 32];
    __shared__ float vs[128 * 32];
    int tid = threadIdx.x;
    for (int idx = tid; idx < 128 * 32; idx += 128) {
        int t = idx >> 5, d = idx & 31;
        int base = (b * 128 + t) * 768 + h * 32 + d;
        ks[idx] = qkv[base + 256];
        vs[idx] = qkv[base + 512];
    }
    __syncthreads();
    int t1 = tid;
    float q[32];
#pragma unroll
    for (int d = 0; d < 32; d++) q[d] = qkv[(b * 128 + t1) * 768 + h * 32 + d];
    float m = -3.4e38f, l = 0.f, acc[32];
#pragma unroll
    for (int d = 0; d < 32; d++) acc[d] = 0.f;
    for (int t2 = 0; t2 <= t1; t2++) {
        float s = 0.f;
#pragma unroll
        for (int d = 0; d < 32; d++) s += q[d] * ks[t2 * 32 + d];
        s *= 0.17677669529663689f;
        float mn = fmaxf(m, s);
        float corr = expf(m - mn);
        float p = expf(s - mn);
        l = l * corr + p;
#pragma unroll
        for (int d = 0; d < 32; d++) acc[d] = acc[d] * corr + p * vs[t2 * 32 + d];
        m = mn;
    }
    float invl = 1.f / l;
#pragma unroll
    for (int d = 0; d < 32; d++)
        o[(b * 128 + t1) * 256 + h * 32 + d] = acc[d] * invl;
}

// ---------------- tiled SGEMM ----------------
template <int BM, int BN, int TM, int TN, bool BIAS, bool GACT, bool RES, bool NG>
__global__ __launch_bounds__(256) void gemm_k(const float* __restrict__ A,
                                              const float* __restrict__ Bm,
                                              const float* __restrict__ bias,
                                              const float* __restrict__ res,
                                              float* __restrict__ C,
                                              int Mr, int Nr, int Kr,
                                              int lda, int ldb, int ldc) {
    constexpr int BK = 32;
    constexpr int TX = BN / TN, TY = BM / TM;
    static_assert(TX * TY == 256, "grid");
    __shared__ float As[BK][BM + 4];
    __shared__ float Bs[BK][BN];
    int tid = threadIdx.x;
    int tx = tid % TX, ty = tid / TX;
    int bm = blockIdx.y * BM, bn = blockIdx.x * BN;
    float acc[TM][TN];
#pragma unroll
    for (int i = 0; i < TM; i++)
#pragma unroll
        for (int j = 0; j < TN; j++) acc[i][j] = 0.f;

    constexpr int ALOAD = BM * 8 / 256;
    constexpr int BLOAD = BK * BN / 4 / 256;
    for (int k0 = 0; k0 < Kr; k0 += BK) {
#pragma unroll
        for (int i = 0; i < ALOAD; i++) {
            int idx = tid + i * 256;
            int row = idx >> 3, kq = idx & 7;
            float4 v = *(const float4*)(A + (size_t)(bm + row) * lda + k0 + kq * 4);
            As[kq * 4 + 0][row] = v.x;
            As[kq * 4 + 1][row] = v.y;
            As[kq * 4 + 2][row] = v.z;
            As[kq * 4 + 3][row] = v.w;
        }
#pragma unroll
        for (int i = 0; i < BLOAD; i++) {
            int idx = tid + i * 256;
            int kr = idx / (BN / 4), nq = idx % (BN / 4);
            int col = bn + nq * 4;
            float4 v;
            if (!NG || col + 4 <= Nr) {
                v = *(const float4*)(Bm + (size_t)(k0 + kr) * ldb + col);
            } else {
                const float* bp = Bm + (size_t)(k0 + kr) * ldb;
                v.x = (col + 0 < Nr) ? bp[col + 0] : 0.f;
                v.y = (col + 1 < Nr) ? bp[col + 1] : 0.f;
                v.z = (col + 2 < Nr) ? bp[col + 2] : 0.f;
                v.w = (col + 3 < Nr) ? bp[col + 3] : 0.f;
            }
            *(float4*)(&Bs[kr][nq * 4]) = v;
        }
        __syncthreads();
#pragma unroll
        for (int k = 0; k < BK; k++) {
            float a[TM], bv[TN];
#pragma unroll
            for (int i = 0; i < TM / 4; i++)
                *(float4*)(a + i * 4) = *(const float4*)(&As[k][ty * TM + i * 4]);
#pragma unroll
            for (int j = 0; j < TN / 4; j++)
                *(float4*)(bv + j * 4) = *(const float4*)(&Bs[k][tx * TN + j * 4]);
#pragma unroll
            for (int i = 0; i < TM; i++)
#pragma unroll
                for (int j = 0; j < TN; j++) acc[i][j] += a[i] * bv[j];
        }
        __syncthreads();
    }
#pragma unroll
    for (int i = 0; i < TM; i++) {
        int r = bm + ty * TM + i;
#pragma unroll
        for (int j = 0; j < TN; j++) {
            int c = bn + tx * TN + j;
            if (NG && c >= Nr) continue;
            float v = acc[i][j];
            if (BIAS) v += bias[c];
            if (GACT) v = geluf(v);
            if (RES) v += res[(size_t)r * ldc + c];
            C[(size_t)r * ldc + c] = v;
        }
    }
}

// ---------------- misc small kernels ----------------
__global__ __launch_bounds__(256) void clear_k(float* __restrict__ rvh, int* __restrict__ flg) {
    int i = blockIdx.x * 256 + threadIdx.x;
    if (i < 4 * 129 * 128) rvh[i] = 0.f;
    if (i < 16) flg[i] = 0;
}
__global__ __launch_bounds__(256) void copy_rv_k(const float* __restrict__ rvh, float* __restrict__ A) {
    int i = blockIdx.x * 256 + threadIdx.x;  // 65536
    int d = i & 127, bt = i >> 7;
    int b = bt >> 7, t = bt & 127;
    A[bt * 384 + 256 + d] = rvh[(b * 129 + t) * 128 + d];
}

// ---------------- scan helpers ----------------
__device__ __forceinline__ void top8_extract(float a0, float a1, float* out, int lane) {
#pragma unroll
    for (int it = 0; it < 8; it++) {
        float m = fmaxf(a0, a1);
#pragma unroll
        for (int of = 16; of; of >>= 1) m = fmaxf(m, __shfl_xor_sync(0xffffffffu, m, of));
        unsigned b0 = __ballot_sync(0xffffffffu, a0 == m);
        if (b0) {
            if (lane == (__ffs(b0) - 1)) a0 = -3.4e38f;
        } else {
            unsigned b1 = __ballot_sync(0xffffffffu, a1 == m);
            if (lane == (__ffs(b1) - 1)) a1 = -3.4e38f;
        }
        if (lane == 0) out[it] = m;
    }
}
__device__ __forceinline__ float block_sum(float v, float* scr, int tid) {
#pragma unroll
    for (int of = 16; of; of >>= 1) v += __shfl_xor_sync(0xffffffffu, v, of);
    if ((tid & 31) == 0) scr[tid >> 5] = v;
    __syncthreads();
    if (tid == 0) {
        float s = 0.f;
#pragma unroll
        for (int i = 0; i < 8; i++) s += scr[i];
        scr[8] = s;
    }
    __syncthreads();
    return scr[8];
}

#define SMEM_SCAN ((512 * 33 + 128 * 129 + 128 + 132 + 512 + 512 + 64 + 32 + 32 + 256) * 4)

__global__ __launch_bounds__(256) void scan_k(const float* __restrict__ ifh,
                                              const float* __restrict__ Wif_g,
                                              const float* __restrict__ br_p,
                                              const float* __restrict__ bw_p,
                                              float* __restrict__ rvh,
                                              int* __restrict__ flg) {
    int b = blockIdx.x >> 2, h = blockIdx.x & 3;
    int tid = threadIdx.x;
    int lane = tid & 31, wid = tid >> 5;
    extern __shared__ float sm[];
    float* M    = sm;                  // 512*33
    float* Wif  = M + 512 * 33;        // 128*129
    float* rv   = Wif + 128 * 129;     // 128
    float* ifc  = rv + 128;            // 132
    float* Sr   = ifc + 132;           // 512
    float* Sw   = Sr + 512;            // 512
    float* cand = Sw + 512;            // 64
    float* redf = cand + 64;           // 32 (top8 out + sums)
    float* er   = redf + 32;           // 32
    float* pscr = er + 32;             // 256

    for (int i = tid; i < 512 * 33; i += 256) M[i] = 0.f;
    for (int i = tid; i < 128 * 129; i += 256) {
        int d = i / 129, j = i - d * 129;
        Wif[i] = Wif_g[(256 + d) * IFW + h * 129 + j];
    }
    float xr = br_p[0], xw = bw_p[0];
    float beta_r = fminf(fmaxf(xr > 20.f ? xr : log1pf(expf(xr)), 1.f), 20.f);
    float beta_w = fminf(fmaxf(xw > 20.f ? xw : log1pf(expf(xw)), 1.f), 20.f);
    __syncthreads();

    const int fb = b * 4;
    for (int t = 0; t < 128; t++) {
        if (t > 0) {
            if (tid < 4) {
                while (atomicAdd(&flg[fb + tid], 0) < t) {}
                __threadfence();
            }
            __syncthreads();
        }
        if (tid < 128) rv[tid] = rvh[(b * 129 + t) * 128 + tid];
        __syncthreads();
        if (tid < 129) {
            float acc = ifh[(b * 128 + t) * IFW + h * 129 + tid];
#pragma unroll 8
            for (int d = 0; d < 128; d++) acc += rv[d] * Wif[d * 129 + tid];
            ifc[tid] = acc;
        }
        __syncthreads();
        // scores (both keys, one M pass)
        {
            int s0 = tid, s1 = tid + 256;
            float sr0 = 0, sw0 = 0, sr1 = 0, sw1 = 0;
#pragma unroll 8
            for (int d = 0; d < 32; d++) {
                float rk = ifc[d], wk = ifc[32 + d];
                float m0 = M[s0 * 33 + d], m1 = M[s1 * 33 + d];
                sr0 += rk * m0; sw0 += wk * m0;
                sr1 += rk * m1; sw1 += wk * m1;
            }
            Sr[s0] = sr0 * beta_r; Sw[s0] = sw0 * beta_w;
            Sr[s1] = sr1 * beta_r; Sw[s1] = sw1 * beta_w;
        }
        if (tid < 32) er[tid] = sigmoidf_(ifc[96 + tid]);
        __syncthreads();

        // ---- READ side ----
        top8_extract(Sr[wid * 64 + lane], Sr[wid * 64 + 32 + lane], cand + wid * 8, lane);
        __syncthreads();
        if (tid < 32) top8_extract(cand[lane], cand[32 + lane], redf, lane);
        __syncthreads();
        {
            float mx = redf[0], thr = redf[7];
            int s0 = tid, s1 = tid + 256;
            float v0 = Sr[s0], v1 = Sr[s1];
            float e0 = (v0 >= thr) ? expf(v0 - mx) : 0.f;
            float e1 = (v1 >= thr) ? expf(v1 - mx) : 0.f;
            __syncthreads();
            Sr[s0] = e0; Sr[s1] = e1;
            float sum = block_sum(e0 + e1, redf + 9, tid);
            float inv = 1.f / sum;
            __syncthreads();
            // dense weighted read: 8 groups x 32 dims
            int g = wid, d = lane;
            float p = 0.f;
#pragma unroll 4
            for (int i = 0; i < 64; i++) {
                int s = g * 64 + i;
                p += Sr[s] * M[s * 33 + d];
            }
            pscr[g * 32 + d] = p;
            __syncthreads();
            if (tid < 32) {
                float r = 0.f;
#pragma unroll
                for (int gg = 0; gg < 8; gg++) r += pscr[gg * 32 + tid];
                float rvn = rv[h * 32 + tid] + r * inv;
                rvh[(b * 129 + t + 1) * 128 + h * 32 + tid] = rvn;
            }
        }
        __syncthreads();

        // ---- WRITE side ----
        top8_extract(Sw[wid * 64 + lane], Sw[wid * 64 + 32 + lane], cand + wid * 8, lane);
        __syncthreads();
        if (tid < 32) top8_extract(cand[lane], cand[32 + lane], redf, lane);
        __syncthreads();
        {
            float mx = redf[0], thr = redf[7];
            int s0 = tid, s1 = tid + 256;
            float v0 = Sw[s0], v1 = Sw[s1];
            float e0 = (v0 >= thr) ? expf(v0 - mx) : 0.f;
            float e1 = (v1 >= thr) ? expf(v1 - mx) : 0.f;
            __syncthreads();
            Sw[s0] = e0; Sw[s1] = e1;
            float sum = block_sum(e0 + e1, redf + 9, tid);
            float invw = 1.f / sum;
            __syncthreads();
            float addg = sigmoidf_(ifc[128]);
#pragma unroll
            for (int i = 0; i < 64; i++) {
                int idx = tid + i * 256;
                int s = idx >> 5, d = idx & 31;
                float w = Sw[s] * invw;
                float wv = ifc[64 + d];
                M[s * 33 + d] = M[s * 33 + d] * (1.f - w * er[d]) + addg * w * wv;
            }
        }
        __threadfence();
        __syncthreads();
        if (tid == 0) atomicExch(&flg[fb + h], t + 1);
    }
}

// ---------------- host launch ----------------
extern "C" void kernel_launch(void* const* d_in, const int* in_sizes, int n_in,
                              void* d_out, int out_size) {
    const int*   ids  = (const int*)d_in[0];
    const float* tok  = (const float*)d_in[1];
    const float* pos  = (const float*)d_in[2];
    const float* Wqkv = (const float*)d_in[3];
    const float* Wo   = (const float*)d_in[4];
    const float* l1g  = (const float*)d_in[5];
    const float* l1b  = (const float*)d_in[6];
    const float* l2g  = (const float*)d_in[7];
    const float* l2b  = (const float*)d_in[8];
    const float* W1   = (const float*)d_in[9];
    const float* b1   = (const float*)d_in[10];
    const float* W2   = (const float*)d_in[11];
    const float* b2   = (const float*)d_in[12];
    const float* lfg  = (const float*)d_in[13];
    const float* lfb  = (const float*)d_in[14];
    const float* WL   = (const float*)d_in[15];
    const float* bL   = (const float*)d_in[16];
    const float* WI   = (const float*)d_in[17];
    const float* bI   = (const float*)d_in[18];
    const float* br   = (const float*)d_in[19];
    const float* bw   = (const float*)d_in[20];
    float* out = (float*)d_out;

    float *x, *h, *qkv, *o, *ff, *A, *ifh, *rvh;
    int* flg;
    cudaGetSymbolAddress((void**)&x, g_x);
    cudaGetSymbolAddress((void**)&h, g_h);
    cudaGetSymbolAddress((void**)&qkv, g_qkv);
    cudaGetSymbolAddress((void**)&o, g_o);
    cudaGetSymbolAddress((void**)&ff, g_ff);
    cudaGetSymbolAddress((void**)&A, g_A);
    cudaGetSymbolAddress((void**)&ifh, g_ifh);
    cudaGetSymbolAddress((void**)&rvh, g_rvh);
    cudaGetSymbolAddress((void**)&flg, g_flags);

    cudaFuncSetAttribute(scan_k, cudaFuncAttributeMaxDynamicSharedMemorySize, SMEM_SCAN);

    clear_k<<<259, 256>>>(rvh, flg);
    embed_k<<<512, 256>>>(ids, tok, pos, x);

    for (int l = 0; l < 2; l++) {
        ln_k<<<64, 256>>>(x, l1g + l * 256, l1b + l * 256, h, 256);
        gemm_k<64, 64, 4, 4, false, false, false, false>
            <<<dim3(12, 8), 256>>>(h, Wqkv + l * 256 * 768, nullptr, nullptr, qkv,
                                   512, 768, 256, 256, 768, 768);
        attn_k<<<32, 128>>>(qkv, o);
        gemm_k<64, 64, 4, 4, false, false, true, false>
            <<<dim3(4, 8), 256>>>(o, Wo + l * 256 * 256, nullptr, x, x,
                                  512, 256, 256, 256, 256, 256);
        ln_k<<<64, 256>>>(x, l2g + l * 256, l2b + l * 256, h, 256);
        gemm_k<64, 64, 4, 4, true, true, false, false>
            <<<dim3(16, 8), 256>>>(h, W1 + l * 256 * 1024, b1 + l * 1024, nullptr, ff,
                                   512, 1024, 256, 256, 1024, 1024);
        gemm_k<64, 64, 4, 4, true, false, true, false>
            <<<dim3(4, 8), 256>>>(ff, W2 + l * 1024 * 256, b2 + l * 256, x, x,
                                  512, 256, 1024, 1024, 256, 256);
    }
    // final LN into concat buffer cols [0,256)
    ln_k<<<64, 256>>>(x, lfg, lfb, A, 384);
    // iface_h = h @ W_iface[0:256] + b_iface
    gemm_k<64, 64, 4, 4, true, false, false, true>
        <<<dim3(9, 8), 256>>>(A, WI, bI, nullptr, ifh, 512, 516, 256, 384, 516, 516);
    // sequential memory scan (16 persistent CTAs)
    scan_k<<<16, 256, SMEM_SCAN>>>(ifh, WI, br, bw, rvh, flg);
    // rv history into concat cols [256,384)
    copy_rv_k<<<256, 256>>>(rvh, A);
    // logits = [h | rv] @ W_logits + b_logits
    gemm_k<128, 128, 8, 8, true, false, false, false>
        <<<dim3(250, 4), 256>>>(A, WL, bL, nullptr, out, 512, 32000, 384, 384, 32000, 32000);
}

// round 6
// speedup vs baseline: 1.0514x; 1.0514x over previous
#include <cuda_runtime.h>
#include <cuda_bf16.h>
#include <math.h>
#include <stdint.h>

#define Bsz 4
#define Tq  128
#define Dm  256
#define FFd 1024
#define NHa 8
#define VOC 32000
#define MDm 128
#define MHh 4
#define HDm 32
#define SLT 512
#define CD  384
#define IFW 516   // MH*(4*HD+1)
#define KCAT 1152 // 3*384

// ---------------- device scratch ----------------
__device__ float g_x[512 * 256];
__device__ float g_h[512 * 256];
__device__ float g_qkv[512 * 768];
__device__ float g_o[512 * 256];
__device__ float g_ff[512 * 1024];
__device__ float g_A[512 * 384];
__device__ float g_ifh[512 * 516];
__device__ float g_rvh[4 * 129 * 128];
__device__ int   g_flags[16];
__device__ __nv_bfloat16 g_Acat[512 * KCAT];
__device__ __nv_bfloat16 g_Bcat[(size_t)VOC * KCAT];

// ---------------- helpers ----------------
__device__ __forceinline__ float geluf(float v) {
    float c = v + 0.044715f * v * v * v;
    return 0.5f * v * (1.f + tanhf(0.7978845608028654f * c));
}
__device__ __forceinline__ float sigmoidf_(float x) { return 1.f / (1.f + expf(-x)); }
__device__ __forceinline__ uint32_t smem_u32(const void* p) {
    uint32_t a;
    asm("{ .reg .u64 t; cvta.to.shared.u64 t, %1; cvt.u32.u64 %0, t; }" : "=r"(a) : "l"(p));
    return a;
}

// ---------------- embedding ----------------
__global__ __launch_bounds__(256) void embed_k(const int* __restrict__ ids,
                                               const float* __restrict__ tok,
                                               const float* __restrict__ pos,
                                               float* __restrict__ x) {
    int i = blockIdx.x * 256 + threadIdx.x;  // 131072
    int d = i & 255, bt = i >> 8, t = bt & 127;
    x[i] = tok[ids[bt] * 256 + d] + pos[t * 256 + d];
}

// ---------------- layernorm (1 warp per row of 256) ----------------
__global__ __launch_bounds__(256) void ln_k(const float* __restrict__ x,
                                            const float* __restrict__ g,
                                            const float* __restrict__ b,
                                            float* __restrict__ o, int ldc) {
    int row = blockIdx.x * 8 + (threadIdx.x >> 5);
    int lane = threadIdx.x & 31;
    const float* xr = x + row * 256;
    float v[8];
    float s = 0.f;
#pragma unroll
    for (int i = 0; i < 8; i++) { v[i] = xr[lane + 32 * i]; s += v[i]; }
#pragma unroll
    for (int of = 16; of; of >>= 1) s += __shfl_xor_sync(0xffffffffu, s, of);
    float m = s * (1.f / 256.f);
    float q = 0.f;
#pragma unroll
    for (int i = 0; i < 8; i++) { float d = v[i] - m; q += d * d; }
#pragma unroll
    for (int of = 16; of; of >>= 1) q += __shfl_xor_sync(0xffffffffu, q, of);
    float inv = rsqrtf(q * (1.f / 256.f) + 1e-5f);
#pragma unroll
    for (int i = 0; i < 8; i++) {
        int c = lane + 32 * i;
        o[row * ldc + c] = (v[i] - m) * inv * g[c] + b[c];
    }
}

// ---------------- attention: CTA per (b, head) ----------------
__global__ __launch_bounds__(128) void attn_k(const float* __restrict__ qkv,
                                              float* __restrict__ o) {
    int b = blockIdx.x >> 3, h = blockIdx.x & 7;
    __shared__ float ks[128 * 32];
    __shared__ float vs[128 * 32];
    int tid = threadIdx.x;
    for (int idx = tid; idx < 128 * 32; idx += 128) {
        int t = idx >> 5, d = idx & 31;
        int base = (b * 128 + t) * 768 + h * 32 + d;
        ks[idx] = qkv[base + 256];
        vs[idx] = qkv[base + 512];
    }
    __syncthreads();
    int t1 = tid;
    float q[32];
#pragma unroll
    for (int d = 0; d < 32; d++) q[d] = qkv[(b * 128 + t1) * 768 + h * 32 + d];
    float m = -3.4e38f, l = 0.f, acc[32];
#pragma unroll
    for (int d = 0; d < 32; d++) acc[d] = 0.f;
    for (int t2 = 0; t2 <= t1; t2++) {
        float s = 0.f;
#pragma unroll
        for (int d = 0; d < 32; d++) s += q[d] * ks[t2 * 32 + d];
        s *= 0.17677669529663689f;
        float mn = fmaxf(m, s);
        float corr = expf(m - mn);
        float p = expf(s - mn);
        l = l * corr + p;
#pragma unroll
        for (int d = 0; d < 32; d++) acc[d] = acc[d] * corr + p * vs[t2 * 32 + d];
        m = mn;
    }
    float invl = 1.f / l;
#pragma unroll
    for (int d = 0; d < 32; d++)
        o[(b * 128 + t1) * 256 + h * 32 + d] = acc[d] * invl;
}

// ---------------- tiled SGEMM (transformer-sized) ----------------
template <int BM, int BN, int TM, int TN, bool BIAS, bool GACT, bool RES, bool NG>
__global__ __launch_bounds__(256) void gemm_k(const float* __restrict__ A,
                                              const float* __restrict__ Bm,
                                              const float* __restrict__ bias,
                                              const float* __restrict__ res,
                                              float* __restrict__ C,
                                              int Mr, int Nr, int Kr,
                                              int lda, int ldb, int ldc) {
    constexpr int BK = 32;
    constexpr int TX = BN / TN, TY = BM / TM;
    static_assert(TX * TY == 256, "grid");
    __shared__ float As[BK][BM + 4];
    __shared__ float Bs[BK][BN];
    int tid = threadIdx.x;
    int tx = tid % TX, ty = tid / TX;
    int bm = blockIdx.y * BM, bn = blockIdx.x * BN;
    float acc[TM][TN];
#pragma unroll
    for (int i = 0; i < TM; i++)
#pragma unroll
        for (int j = 0; j < TN; j++) acc[i][j] = 0.f;

    constexpr int ALOAD = BM * 8 / 256;
    constexpr int BLOAD = BK * BN / 4 / 256;
    for (int k0 = 0; k0 < Kr; k0 += BK) {
#pragma unroll
        for (int i = 0; i < ALOAD; i++) {
            int idx = tid + i * 256;
            int row = idx >> 3, kq = idx & 7;
            float4 v = *(const float4*)(A + (size_t)(bm + row) * lda + k0 + kq * 4);
            As[kq * 4 + 0][row] = v.x;
            As[kq * 4 + 1][row] = v.y;
            As[kq * 4 + 2][row] = v.z;
            As[kq * 4 + 3][row] = v.w;
        }
#pragma unroll
        for (int i = 0; i < BLOAD; i++) {
            int idx = tid + i * 256;
            int kr = idx / (BN / 4), nq = idx % (BN / 4);
            int col = bn + nq * 4;
            float4 v;
            if (!NG || col + 4 <= Nr) {
                v = *(const float4*)(Bm + (size_t)(k0 + kr) * ldb + col);
            } else {
                const float* bp = Bm + (size_t)(k0 + kr) * ldb;
                v.x = (col + 0 < Nr) ? bp[col + 0] : 0.f;
                v.y = (col + 1 < Nr) ? bp[col + 1] : 0.f;
                v.z = (col + 2 < Nr) ? bp[col + 2] : 0.f;
                v.w = (col + 3 < Nr) ? bp[col + 3] : 0.f;
            }
            *(float4*)(&Bs[kr][nq * 4]) = v;
        }
        __syncthreads();
#pragma unroll
        for (int k = 0; k < BK; k++) {
            float a[TM], bv[TN];
#pragma unroll
            for (int i = 0; i < TM / 4; i++)
                *(float4*)(a + i * 4) = *(const float4*)(&As[k][ty * TM + i * 4]);
#pragma unroll
            for (int j = 0; j < TN / 4; j++)
                *(float4*)(bv + j * 4) = *(const float4*)(&Bs[k][tx * TN + j * 4]);
#pragma unroll
            for (int i = 0; i < TM; i++)
#pragma unroll
                for (int j = 0; j < TN; j++) acc[i][j] += a[i] * bv[j];
        }
        __syncthreads();
    }
#pragma unroll
    for (int i = 0; i < TM; i++) {
        int r = bm + ty * TM + i;
#pragma unroll
        for (int j = 0; j < TN; j++) {
            int c = bn + tx * TN + j;
            if (NG && c >= Nr) continue;
            float v = acc[i][j];
            if (BIAS) v += bias[c];
            if (GACT) v = geluf(v);
            if (RES) v += res[(size_t)r * ldc + c];
            C[(size_t)r * ldc + c] = v;
        }
    }
}

// ---------------- misc small kernels ----------------
__global__ __launch_bounds__(256) void clear_k(float* __restrict__ rvh, int* __restrict__ flg) {
    int i = blockIdx.x * 256 + threadIdx.x;
    if (i < 4 * 129 * 128) rvh[i] = 0.f;
    if (i < 16) flg[i] = 0;
}
__global__ __launch_bounds__(256) void copy_rv_k(const float* __restrict__ rvh, float* __restrict__ A) {
    int i = blockIdx.x * 256 + threadIdx.x;  // 65536
    int d = i & 127, bt = i >> 7;
    int b = bt >> 7, t = bt & 127;
    A[bt * 384 + 256 + d] = rvh[(b * 129 + t) * 128 + d];
}

// ---------------- bf16 split prep ----------------
// A' = [Ah | Al | Ah], B' = [Bh | Bh | Bl]  ->  A'B' = AhBh + AlBh + AhBl
__global__ __launch_bounds__(256) void prepA_k(const float* __restrict__ A,
                                               __nv_bfloat16* __restrict__ Acat) {
    int i = blockIdx.x * 256 + threadIdx.x;  // 512*384 = 196608
    int k = i % CD, m = i / CD;
    float x = A[i];
    __nv_bfloat16 h = __float2bfloat16(x);
    __nv_bfloat16 l = __float2bfloat16(x - __bfloat162float(h));
    __nv_bfloat16* row = Acat + (size_t)m * KCAT;
    row[k] = h;
    row[CD + k] = l;
    row[2 * CD + k] = h;
}
__global__ __launch_bounds__(256) void prepB_k(const float* __restrict__ W,
                                               __nv_bfloat16* __restrict__ Bcat) {
    __shared__ float t[32][33];
    int n0 = blockIdx.x * 32, k0 = blockIdx.y * 32;
    int tx = threadIdx.x & 31, ty = threadIdx.x >> 5;  // 32 x 8
#pragma unroll
    for (int i = 0; i < 32; i += 8)
        t[ty + i][tx] = W[(size_t)(k0 + ty + i) * VOC + n0 + tx];
    __syncthreads();
#pragma unroll
    for (int i = 0; i < 32; i += 8) {
        int n = n0 + ty + i, k = k0 + tx;
        float x = t[tx][ty + i];
        __nv_bfloat16 h = __float2bfloat16(x);
        __nv_bfloat16 l = __float2bfloat16(x - __bfloat162float(h));
        __nv_bfloat16* row = Bcat + (size_t)n * KCAT;
        row[k] = h;
        row[CD + k] = h;
        row[2 * CD + k] = l;
    }
}

// ---------------- logits GEMM via mma.sync (bf16, f32 acc) ----------------
// CTA 128x128, 8 warps (2x4), warp tile 64x32, BK=32. smem rows padded to 40 halves.
__device__ __forceinline__ void ldsm4(uint32_t* r, uint32_t addr) {
    asm volatile("ldmatrix.sync.aligned.m8n8.x4.shared.b16 {%0,%1,%2,%3}, [%4];"
                 : "=r"(r[0]), "=r"(r[1]), "=r"(r[2]), "=r"(r[3]) : "r"(addr));
}
__device__ __forceinline__ void ldsm2(uint32_t* r, uint32_t addr) {
    asm volatile("ldmatrix.sync.aligned.m8n8.x2.shared.b16 {%0,%1}, [%2];"
                 : "=r"(r[0]), "=r"(r[1]) : "r"(addr));
}
__device__ __forceinline__ void mma16816(float* c, const uint32_t* a, const uint32_t* b) {
    asm volatile(
        "mma.sync.aligned.m16n8k16.row.col.f32.bf16.bf16.f32 "
        "{%0,%1,%2,%3}, {%4,%5,%6,%7}, {%8,%9}, {%0,%1,%2,%3};"
        : "+f"(c[0]), "+f"(c[1]), "+f"(c[2]), "+f"(c[3])
        : "r"(a[0]), "r"(a[1]), "r"(a[2]), "r"(a[3]), "r"(b[0]), "r"(b[1]));
}

__global__ __launch_bounds__(256) void logits_mma_k(const __nv_bfloat16* __restrict__ Acat,
                                                    const __nv_bfloat16* __restrict__ Bcat,
                                                    const float* __restrict__ bias,
                                                    float* __restrict__ out) {
    __shared__ __align__(16) __nv_bfloat16 As[128 * 40];
    __shared__ __align__(16) __nv_bfloat16 Bs[128 * 40];
    int tid = threadIdx.x, wid = tid >> 5, lane = tid & 31;
    int m0 = blockIdx.y * 128, n0 = blockIdx.x * 128;
    int wm = wid >> 2, wn = wid & 3;   // warp -> (m 0..1, n 0..3)

    float acc[4][4][4];
#pragma unroll
    for (int mt = 0; mt < 4; mt++)
#pragma unroll
        for (int nt = 0; nt < 4; nt++)
#pragma unroll
            for (int i = 0; i < 4; i++) acc[mt][nt][i] = 0.f;

    uint32_t a_base = smem_u32(As);
    uint32_t b_base = smem_u32(Bs);
    // per-lane ldmatrix row/col selectors
    int a_r = (lane & 7) + ((lane >> 3) & 1) * 8;   // row within 16
    int a_c = (lane >> 4) * 8;                      // k offset 0/8
    int b_r = lane & 7;
    int b_c = ((lane >> 3) & 1) * 8;

    for (int k0 = 0; k0 < KCAT; k0 += 32) {
#pragma unroll
        for (int j = 0; j < 2; j++) {
            int idx = tid + j * 256;
            int row = idx >> 2, ci = idx & 3;
            *(uint4*)(As + row * 40 + ci * 8) =
                *(const uint4*)(Acat + (size_t)(m0 + row) * KCAT + k0 + ci * 8);
            *(uint4*)(Bs + row * 40 + ci * 8) =
                *(const uint4*)(Bcat + (size_t)(n0 + row) * KCAT + k0 + ci * 8);
        }
        __syncthreads();
#pragma unroll
        for (int ks = 0; ks < 2; ks++) {
            int kb = ks * 16;
            uint32_t af[4][4], bf[4][2];
#pragma unroll
            for (int mt = 0; mt < 4; mt++)
                ldsm4(af[mt], a_base + (uint32_t)(((wm * 64 + mt * 16 + a_r) * 40 + kb + a_c) * 2));
#pragma unroll
            for (int nt = 0; nt < 4; nt++)
                ldsm2(bf[nt], b_base + (uint32_t)(((wn * 32 + nt * 8 + b_r) * 40 + kb + b_c) * 2));
#pragma unroll
            for (int mt = 0; mt < 4; mt++)
#pragma unroll
                for (int nt = 0; nt < 4; nt++)
                    mma16816(acc[mt][nt], af[mt], bf[nt]);
        }
        __syncthreads();
    }
    // epilogue
    int r = lane >> 2, cp = (lane & 3) * 2;
#pragma unroll
    for (int mt = 0; mt < 4; mt++) {
        int grow = m0 + wm * 64 + mt * 16 + r;
#pragma unroll
        for (int nt = 0; nt < 4; nt++) {
            int gcol = n0 + wn * 32 + nt * 8 + cp;
            float b0 = bias[gcol], b1 = bias[gcol + 1];
            float2 v0 = make_float2(acc[mt][nt][0] + b0, acc[mt][nt][1] + b1);
            float2 v1 = make_float2(acc[mt][nt][2] + b0, acc[mt][nt][3] + b1);
            *(float2*)(out + (size_t)grow * VOC + gcol) = v0;
            *(float2*)(out + (size_t)(grow + 8) * VOC + gcol) = v1;
        }
    }
}

// ---------------- scan helpers ----------------
__device__ __forceinline__ void top8_extract(float a0, float a1, float* out, int lane) {
#pragma unroll
    for (int it = 0; it < 8; it++) {
        float m = fmaxf(a0, a1);
#pragma unroll
        for (int of = 16; of; of >>= 1) m = fmaxf(m, __shfl_xor_sync(0xffffffffu, m, of));
        unsigned b0 = __ballot_sync(0xffffffffu, a0 == m);
        if (b0) {
            if (lane == (__ffs(b0) - 1)) a0 = -3.4e38f;
        } else {
            unsigned b1 = __ballot_sync(0xffffffffu, a1 == m);
            if (lane == (__ffs(b1) - 1)) a1 = -3.4e38f;
        }
        if (lane == 0) out[it] = m;
    }
}
__device__ __forceinline__ float block_sum(float v, float* scr, int tid) {
#pragma unroll
    for (int of = 16; of; of >>= 1) v += __shfl_xor_sync(0xffffffffu, v, of);
    if ((tid & 31) == 0) scr[tid >> 5] = v;
    __syncthreads();
    if (tid == 0) {
        float s = 0.f;
#pragma unroll
        for (int i = 0; i < 8; i++) s += scr[i];
        scr[8] = s;
    }
    __syncthreads();
    return scr[8];
}

#define SMEM_SCAN ((512 * 33 + 128 * 129 + 128 + 132 + 512 + 512 + 64 + 32 + 32 + 256) * 4)

__global__ __launch_bounds__(256) void scan_k(const float* __restrict__ ifh,
                                              const float* __restrict__ Wif_g,
                                              const float* __restrict__ br_p,
                                              const float* __restrict__ bw_p,
                                              float* __restrict__ rvh,
                                              int* __restrict__ flg) {
    int b = blockIdx.x >> 2, h = blockIdx.x & 3;
    int tid = threadIdx.x;
    int lane = tid & 31, wid = tid >> 5;
    extern __shared__ float sm[];
    float* M    = sm;                  // 512*33
    float* Wif  = M + 512 * 33;        // 128*129
    float* rv   = Wif + 128 * 129;     // 128
    float* ifc  = rv + 128;            // 132
    float* Sr   = ifc + 132;           // 512
    float* Sw   = Sr + 512;            // 512
    float* cand = Sw + 512;            // 64
    float* redf = cand + 64;           // 32
    float* er   = redf + 32;           // 32
    float* pscr = er + 32;             // 256

    for (int i = tid; i < 512 * 33; i += 256) M[i] = 0.f;
    for (int i = tid; i < 128 * 129; i += 256) {
        int d = i / 129, j = i - d * 129;
        Wif[i] = Wif_g[(256 + d) * IFW + h * 129 + j];
    }
    float xr = br_p[0], xw = bw_p[0];
    float beta_r = fminf(fmaxf(xr > 20.f ? xr : log1pf(expf(xr)), 1.f), 20.f);
    float beta_w = fminf(fmaxf(xw > 20.f ? xw : log1pf(expf(xw)), 1.f), 20.f);
    __syncthreads();

    const int fb = b * 4;
    for (int t = 0; t < 128; t++) {
        if (t > 0) {
            if (tid < 4) {
                volatile int* vf = (volatile int*)(flg + fb + tid);
                while (*vf < t) {}
            }
            __syncthreads();
            __threadfence();
        }
        if (tid < 128) rv[tid] = rvh[(b * 129 + t) * 128 + tid];
        __syncthreads();
        if (tid < 129) {
            float acc = ifh[(b * 128 + t) * IFW + h * 129 + tid];
#pragma unroll 8
            for (int d = 0; d < 128; d++) acc += rv[d] * Wif[d * 129 + tid];
            ifc[tid] = acc;
        }
        __syncthreads();
        {
            int s0 = tid, s1 = tid + 256;
            float sr0 = 0, sw0 = 0, sr1 = 0, sw1 = 0;
#pragma unroll 8
            for (int d = 0; d < 32; d++) {
                float rk = ifc[d], wk = ifc[32 + d];
                float m0 = M[s0 * 33 + d], m1 = M[s1 * 33 + d];
                sr0 += rk * m0; sw0 += wk * m0;
                sr1 += rk * m1; sw1 += wk * m1;
            }
            Sr[s0] = sr0 * beta_r; Sw[s0] = sw0 * beta_w;
            Sr[s1] = sr1 * beta_r; Sw[s1] = sw1 * beta_w;
        }
        if (tid < 32) er[tid] = sigmoidf_(ifc[96 + tid]);
        __syncthreads();

        // READ
        top8_extract(Sr[wid * 64 + lane], Sr[wid * 64 + 32 + lane], cand + wid * 8, lane);
        __syncthreads();
        if (tid < 32) top8_extract(cand[lane], cand[32 + lane], redf, lane);
        __syncthreads();
        {
            float mx = redf[0], thr = redf[7];
            int s0 = tid, s1 = tid + 256;
            float v0 = Sr[s0], v1 = Sr[s1];
            float e0 = (v0 >= thr) ? expf(v0 - mx) : 0.f;
            float e1 = (v1 >= thr) ? expf(v1 - mx) : 0.f;
            __syncthreads();
            Sr[s0] = e0; Sr[s1] = e1;
            float sum = block_sum(e0 + e1, redf + 9, tid);
            float inv = 1.f / sum;
            __syncthreads();
            int g = wid, d = lane;
            float p = 0.f;
#pragma unroll 4
            for (int i = 0; i < 64; i++) {
                int s = g * 64 + i;
                p += Sr[s] * M[s * 33 + d];
            }
            pscr[g * 32 + d] = p;
            __syncthreads();
            if (tid < 32) {
                float r = 0.f;
#pragma unroll
                for (int gg = 0; gg < 8; gg++) r += pscr[gg * 32 + tid];
                float rvn = rv[h * 32 + tid] + r * inv;
                rvh[(b * 129 + t + 1) * 128 + h * 32 + tid] = rvn;
            }
        }
        __syncthreads();

        // WRITE
        top8_extract(Sw[wid * 64 + lane], Sw[wid * 64 + 32 + lane], cand + wid * 8, lane);
        __syncthreads();
        if (tid < 32) top8_extract(cand[lane], cand[32 + lane], redf, lane);
        __syncthreads();
        {
            float mx = redf[0], thr = redf[7];
            int s0 = tid, s1 = tid + 256;
            float v0 = Sw[s0], v1 = Sw[s1];
            float e0 = (v0 >= thr) ? expf(v0 - mx) : 0.f;
            float e1 = (v1 >= thr) ? expf(v1 - mx) : 0.f;
            __syncthreads();
            Sw[s0] = e0; Sw[s1] = e1;
            float sum = block_sum(e0 + e1, redf + 9, tid);
            float invw = 1.f / sum;
            __syncthreads();
            float addg = sigmoidf_(ifc[128]);
#pragma unroll
            for (int i = 0; i < 64; i++) {
                int idx = tid + i * 256;
                int s = idx >> 5, d = idx & 31;
                float w = Sw[s] * invw;
                float wv = ifc[64 + d];
                M[s * 33 + d] = M[s * 33 + d] * (1.f - w * er[d]) + addg * w * wv;
            }
        }
        __threadfence();
        __syncthreads();
        if (tid == 0) atomicExch(&flg[fb + h], t + 1);
    }
}

// ---------------- host launch ----------------
extern "C" void kernel_launch(void* const* d_in, const int* in_sizes, int n_in,
                              void* d_out, int out_size) {
    const int*   ids  = (const int*)d_in[0];
    const float* tok  = (const float*)d_in[1];
    const float* pos  = (const float*)d_in[2];
    const float* Wqkv = (const float*)d_in[3];
    const float* Wo   = (const float*)d_in[4];
    const float* l1g  = (const float*)d_in[5];
    const float* l1b  = (const float*)d_in[6];
    const float* l2g  = (const float*)d_in[7];
    const float* l2b  = (const float*)d_in[8];
    const float* W1   = (const float*)d_in[9];
    const float* b1   = (const float*)d_in[10];
    const float* W2   = (const float*)d_in[11];
    const float* b2   = (const float*)d_in[12];
    const float* lfg  = (const float*)d_in[13];
    const float* lfb  = (const float*)d_in[14];
    const float* WL   = (const float*)d_in[15];
    const float* bL   = (const float*)d_in[16];
    const float* WI   = (const float*)d_in[17];
    const float* bI   = (const float*)d_in[18];
    const float* br   = (const float*)d_in[19];
    const float* bw   = (const float*)d_in[20];
    float* out = (float*)d_out;

    float *x, *h, *qkv, *o, *ff, *A, *ifh, *rvh;
    __nv_bfloat16 *Acat, *Bcat;
    int* flg;
    cudaGetSymbolAddress((void**)&x, g_x);
    cudaGetSymbolAddress((void**)&h, g_h);
    cudaGetSymbolAddress((void**)&qkv, g_qkv);
    cudaGetSymbolAddress((void**)&o, g_o);
    cudaGetSymbolAddress((void**)&ff, g_ff);
    cudaGetSymbolAddress((void**)&A, g_A);
    cudaGetSymbolAddress((void**)&ifh, g_ifh);
    cudaGetSymbolAddress((void**)&rvh, g_rvh);
    cudaGetSymbolAddress((void**)&Acat, g_Acat);
    cudaGetSymbolAddress((void**)&Bcat, g_Bcat);
    cudaGetSymbolAddress((void**)&flg, g_flags);

    cudaFuncSetAttribute(scan_k, cudaFuncAttributeMaxDynamicSharedMemorySize, SMEM_SCAN);

    clear_k<<<259, 256>>>(rvh, flg);
    embed_k<<<512, 256>>>(ids, tok, pos, x);
    // W_logits split/transpose (independent of activations)
    prepB_k<<<dim3(1000, 12), 256>>>(WL, Bcat);

    for (int l = 0; l < 2; l++) {
        ln_k<<<64, 256>>>(x, l1g + l * 256, l1b + l * 256, h, 256);
        gemm_k<64, 64, 4, 4, false, false, false, false>
            <<<dim3(12, 8), 256>>>(h, Wqkv + l * 256 * 768, nullptr, nullptr, qkv,
                                   512, 768, 256, 256, 768, 768);
        attn_k<<<32, 128>>>(qkv, o);
        gemm_k<64, 64, 4, 4, false, false, true, false>
            <<<dim3(4, 8), 256>>>(o, Wo + l * 256 * 256, nullptr, x, x,
                                  512, 256, 256, 256, 256, 256);
        ln_k<<<64, 256>>>(x, l2g + l * 256, l2b + l * 256, h, 256);
        gemm_k<64, 64, 4, 4, true, true, false, false>
            <<<dim3(16, 8), 256>>>(h, W1 + l * 256 * 1024, b1 + l * 1024, nullptr, ff,
                                   512, 1024, 256, 256, 1024, 1024);
        gemm_k<64, 64, 4, 4, true, false, true, false>
            <<<dim3(4, 8), 256>>>(ff, W2 + l * 1024 * 256, b2 + l * 256, x, x,
                                  512, 256, 1024, 1024, 256, 256);
    }
    ln_k<<<64, 256>>>(x, lfg, lfb, A, 384);
    gemm_k<64, 64, 4, 4, true, false, false, true>
        <<<dim3(9, 8), 256>>>(A, WI, bI, nullptr, ifh, 512, 516, 256, 384, 516, 516);
    scan_k<<<16, 256, SMEM_SCAN>>>(ifh, WI, br, bw, rvh, flg);
    copy_rv_k<<<256, 256>>>(rvh, A);
    prepA_k<<<768, 256>>>(A, Acat);
    logits_mma_k<<<dim3(250, 4), 256>>>(Acat, Bcat, bL, out);
}

// round 7
// speedup vs baseline: 1.2661x; 1.2042x over previous
#include <cuda_runtime.h>
#include <cuda_bf16.h>
#include <math.h>
#include <stdint.h>

#define Bsz 4
#define Tq  128
#define Dm  256
#define FFd 1024
#define NHa 8
#define VOC 32000
#define MDm 128
#define MHh 4
#define HDm 32
#define SLT 512
#define CD  384
#define IFW 516   // MH*(4*HD+1)
#define KCAT 1152 // 3*384

// ---------------- device scratch ----------------
__device__ float g_x[512 * 256];
__device__ float g_h[512 * 256];
__device__ float g_qkv[512 * 768];
__device__ float g_o[512 * 256];
__device__ float g_ff[512 * 1024];
__device__ float g_A[512 * 384];
__device__ float g_ifh[512 * 516];
__device__ float g_rvh[4 * 129 * 128];
__device__ int   g_flags[16];
__device__ __nv_bfloat16 g_Acat[512 * KCAT];
__device__ __nv_bfloat16 g_Bcat[(size_t)VOC * KCAT];

// ---------------- helpers ----------------
__device__ __forceinline__ float geluf(float v) {
    float c = v + 0.044715f * v * v * v;
    return 0.5f * v * (1.f + tanhf(0.7978845608028654f * c));
}
__device__ __forceinline__ float sigmoidf_(float x) { return 1.f / (1.f + expf(-x)); }
__device__ __forceinline__ uint32_t smem_u32(const void* p) {
    uint32_t a;
    asm("{ .reg .u64 t; cvta.to.shared.u64 t, %1; cvt.u32.u64 %0, t; }" : "=r"(a) : "l"(p));
    return a;
}

// ---------------- embedding ----------------
__global__ __launch_bounds__(256) void embed_k(const int* __restrict__ ids,
                                               const float* __restrict__ tok,
                                               const float* __restrict__ pos,
                                               float* __restrict__ x) {
    int i = blockIdx.x * 256 + threadIdx.x;  // 131072
    int d = i & 255, bt = i >> 8, t = bt & 127;
    x[i] = tok[ids[bt] * 256 + d] + pos[t * 256 + d];
}

// ---------------- layernorm (1 warp per row of 256) ----------------
__global__ __launch_bounds__(256) void ln_k(const float* __restrict__ x,
                                            const float* __restrict__ g,
                                            const float* __restrict__ b,
                                            float* __restrict__ o, int ldc) {
    int row = blockIdx.x * 8 + (threadIdx.x >> 5);
    int lane = threadIdx.x & 31;
    const float* xr = x + row * 256;
    float v[8];
    float s = 0.f;
#pragma unroll
    for (int i = 0; i < 8; i++) { v[i] = xr[lane + 32 * i]; s += v[i]; }
#pragma unroll
    for (int of = 16; of; of >>= 1) s += __shfl_xor_sync(0xffffffffu, s, of);
    float m = s * (1.f / 256.f);
    float q = 0.f;
#pragma unroll
    for (int i = 0; i < 8; i++) { float d = v[i] - m; q += d * d; }
#pragma unroll
    for (int of = 16; of; of >>= 1) q += __shfl_xor_sync(0xffffffffu, q, of);
    float inv = rsqrtf(q * (1.f / 256.f) + 1e-5f);
#pragma unroll
    for (int i = 0; i < 8; i++) {
        int c = lane + 32 * i;
        o[row * ldc + c] = (v[i] - m) * inv * g[c] + b[c];
    }
}

// ---------------- attention: CTA per (b, head) ----------------
__global__ __launch_bounds__(128) void attn_k(const float* __restrict__ qkv,
                                              float* __restrict__ o) {
    int b = blockIdx.x >> 3, h = blockIdx.x & 7;
    __shared__ float ks[128 * 32];
    __shared__ float vs[128 * 32];
    int tid = threadIdx.x;
    for (int idx = tid; idx < 128 * 32; idx += 128) {
        int t = idx >> 5, d = idx & 31;
        int base = (b * 128 + t) * 768 + h * 32 + d;
        ks[idx] = qkv[base + 256];
        vs[idx] = qkv[base + 512];
    }
    __syncthreads();
    int t1 = tid;
    float q[32];
#pragma unroll
    for (int d = 0; d < 32; d++) q[d] = qkv[(b * 128 + t1) * 768 + h * 32 + d];
    float m = -3.4e38f, l = 0.f, acc[32];
#pragma unroll
    for (int d = 0; d < 32; d++) acc[d] = 0.f;
    for (int t2 = 0; t2 <= t1; t2++) {
        float s = 0.f;
#pragma unroll
        for (int d = 0; d < 32; d++) s += q[d] * ks[t2 * 32 + d];
        s *= 0.17677669529663689f;
        float mn = fmaxf(m, s);
        float corr = expf(m - mn);
        float p = expf(s - mn);
        l = l * corr + p;
#pragma unroll
        for (int d = 0; d < 32; d++) acc[d] = acc[d] * corr + p * vs[t2 * 32 + d];
        m = mn;
    }
    float invl = 1.f / l;
#pragma unroll
    for (int d = 0; d < 32; d++)
        o[(b * 128 + t1) * 256 + h * 32 + d] = acc[d] * invl;
}

// ---------------- tiled SGEMM (transformer-sized) ----------------
template <int BM, int BN, int TM, int TN, bool BIAS, bool GACT, bool RES, bool NG>
__global__ __launch_bounds__(256) void gemm_k(const float* __restrict__ A,
                                              const float* __restrict__ Bm,
                                              const float* __restrict__ bias,
                                              const float* __restrict__ res,
                                              float* __restrict__ C,
                                              int Mr, int Nr, int Kr,
                                              int lda, int ldb, int ldc) {
    constexpr int BK = 32;
    constexpr int TX = BN / TN, TY = BM / TM;
    static_assert(TX * TY == 256, "grid");
    __shared__ float As[BK][BM + 4];
    __shared__ float Bs[BK][BN];
    int tid = threadIdx.x;
    int tx = tid % TX, ty = tid / TX;
    int bm = blockIdx.y * BM, bn = blockIdx.x * BN;
    float acc[TM][TN];
#pragma unroll
    for (int i = 0; i < TM; i++)
#pragma unroll
        for (int j = 0; j < TN; j++) acc[i][j] = 0.f;

    constexpr int ALOAD = BM * 8 / 256;
    constexpr int BLOAD = BK * BN / 4 / 256;
    for (int k0 = 0; k0 < Kr; k0 += BK) {
#pragma unroll
        for (int i = 0; i < ALOAD; i++) {
            int idx = tid + i * 256;
            int row = idx >> 3, kq = idx & 7;
            float4 v = *(const float4*)(A + (size_t)(bm + row) * lda + k0 + kq * 4);
            As[kq * 4 + 0][row] = v.x;
            As[kq * 4 + 1][row] = v.y;
            As[kq * 4 + 2][row] = v.z;
            As[kq * 4 + 3][row] = v.w;
        }
#pragma unroll
        for (int i = 0; i < BLOAD; i++) {
            int idx = tid + i * 256;
            int kr = idx / (BN / 4), nq = idx % (BN / 4);
            int col = bn + nq * 4;
            float4 v;
            if (!NG || col + 4 <= Nr) {
                v = *(const float4*)(Bm + (size_t)(k0 + kr) * ldb + col);
            } else {
                const float* bp = Bm + (size_t)(k0 + kr) * ldb;
                v.x = (col + 0 < Nr) ? bp[col + 0] : 0.f;
                v.y = (col + 1 < Nr) ? bp[col + 1] : 0.f;
                v.z = (col + 2 < Nr) ? bp[col + 2] : 0.f;
                v.w = (col + 3 < Nr) ? bp[col + 3] : 0.f;
            }
            *(float4*)(&Bs[kr][nq * 4]) = v;
        }
        __syncthreads();
#pragma unroll
        for (int k = 0; k < BK; k++) {
            float a[TM], bv[TN];
#pragma unroll
            for (int i = 0; i < TM / 4; i++)
                *(float4*)(a + i * 4) = *(const float4*)(&As[k][ty * TM + i * 4]);
#pragma unroll
            for (int j = 0; j < TN / 4; j++)
                *(float4*)(bv + j * 4) = *(const float4*)(&Bs[k][tx * TN + j * 4]);
#pragma unroll
            for (int i = 0; i < TM; i++)
#pragma unroll
                for (int j = 0; j < TN; j++) acc[i][j] += a[i] * bv[j];
        }
        __syncthreads();
    }
#pragma unroll
    for (int i = 0; i < TM; i++) {
        int r = bm + ty * TM + i;
#pragma unroll
        for (int j = 0; j < TN; j++) {
            int c = bn + tx * TN + j;
            if (NG && c >= Nr) continue;
            float v = acc[i][j];
            if (BIAS) v += bias[c];
            if (GACT) v = geluf(v);
            if (RES) v += res[(size_t)r * ldc + c];
            C[(size_t)r * ldc + c] = v;
        }
    }
}

// ---------------- misc small kernels ----------------
__global__ __launch_bounds__(256) void clear_k(float* __restrict__ rvh, int* __restrict__ flg) {
    int i = blockIdx.x * 256 + threadIdx.x;
    if (i < 4 * 129 * 128) rvh[i] = 0.f;
    if (i < 16) flg[i] = 0;
}
__global__ __launch_bounds__(256) void copy_rv_k(const float* __restrict__ rvh, float* __restrict__ A) {
    int i = blockIdx.x * 256 + threadIdx.x;  // 65536
    int d = i & 127, bt = i >> 7;
    int b = bt >> 7, t = bt & 127;
    A[bt * 384 + 256 + d] = rvh[(b * 129 + t) * 128 + d];
}

// ---------------- bf16 split prep ----------------
__global__ __launch_bounds__(256) void prepA_k(const float* __restrict__ A,
                                               __nv_bfloat16* __restrict__ Acat) {
    int i = blockIdx.x * 256 + threadIdx.x;  // 512*384 = 196608
    int k = i % CD, m = i / CD;
    float x = A[i];
    __nv_bfloat16 h = __float2bfloat16(x);
    __nv_bfloat16 l = __float2bfloat16(x - __bfloat162float(h));
    __nv_bfloat16* row = Acat + (size_t)m * KCAT;
    row[k] = h;
    row[CD + k] = l;
    row[2 * CD + k] = h;
}
__global__ __launch_bounds__(256) void prepB_k(const float* __restrict__ W,
                                               __nv_bfloat16* __restrict__ Bcat) {
    __shared__ float t[32][33];
    int n0 = blockIdx.x * 32, k0 = blockIdx.y * 32;
    int tx = threadIdx.x & 31, ty = threadIdx.x >> 5;  // 32 x 8
#pragma unroll
    for (int i = 0; i < 32; i += 8)
        t[ty + i][tx] = W[(size_t)(k0 + ty + i) * VOC + n0 + tx];
    __syncthreads();
#pragma unroll
    for (int i = 0; i < 32; i += 8) {
        int n = n0 + ty + i, k = k0 + tx;
        float x = t[tx][ty + i];
        __nv_bfloat16 h = __float2bfloat16(x);
        __nv_bfloat16 l = __float2bfloat16(x - __bfloat162float(h));
        __nv_bfloat16* row = Bcat + (size_t)n * KCAT;
        row[k] = h;
        row[CD + k] = h;
        row[2 * CD + k] = l;
    }
}

// ---------------- logits GEMM via mma.sync (bf16, f32 acc) ----------------
__device__ __forceinline__ void ldsm4(uint32_t* r, uint32_t addr) {
    asm volatile("ldmatrix.sync.aligned.m8n8.x4.shared.b16 {%0,%1,%2,%3}, [%4];"
                 : "=r"(r[0]), "=r"(r[1]), "=r"(r[2]), "=r"(r[3]) : "r"(addr));
}
__device__ __forceinline__ void ldsm2(uint32_t* r, uint32_t addr) {
    asm volatile("ldmatrix.sync.aligned.m8n8.x2.shared.b16 {%0,%1}, [%2];"
                 : "=r"(r[0]), "=r"(r[1]) : "r"(addr));
}
__device__ __forceinline__ void mma16816(float* c, const uint32_t* a, const uint32_t* b) {
    asm volatile(
        "mma.sync.aligned.m16n8k16.row.col.f32.bf16.bf16.f32 "
        "{%0,%1,%2,%3}, {%4,%5,%6,%7}, {%8,%9}, {%0,%1,%2,%3};"
        : "+f"(c[0]), "+f"(c[1]), "+f"(c[2]), "+f"(c[3])
        : "r"(a[0]), "r"(a[1]), "r"(a[2]), "r"(a[3]), "r"(b[0]), "r"(b[1]));
}

__global__ __launch_bounds__(256) void logits_mma_k(const __nv_bfloat16* __restrict__ Acat,
                                                    const __nv_bfloat16* __restrict__ Bcat,
                                                    const float* __restrict__ bias,
                                                    float* __restrict__ out) {
    __shared__ __align__(16) __nv_bfloat16 As[128 * 40];
    __shared__ __align__(16) __nv_bfloat16 Bs[128 * 40];
    int tid = threadIdx.x, wid = tid >> 5, lane = tid & 31;
    int m0 = blockIdx.y * 128, n0 = blockIdx.x * 128;
    int wm = wid >> 2, wn = wid & 3;

    float acc[4][4][4];
#pragma unroll
    for (int mt = 0; mt < 4; mt++)
#pragma unroll
        for (int nt = 0; nt < 4; nt++)
#pragma unroll
            for (int i = 0; i < 4; i++) acc[mt][nt][i] = 0.f;

    uint32_t a_base = smem_u32(As);
    uint32_t b_base = smem_u32(Bs);
    int a_r = (lane & 7) + ((lane >> 3) & 1) * 8;
    int a_c = (lane >> 4) * 8;
    int b_r = lane & 7;
    int b_c = ((lane >> 3) & 1) * 8;

    for (int k0 = 0; k0 < KCAT; k0 += 32) {
#pragma unroll
        for (int j = 0; j < 2; j++) {
            int idx = tid + j * 256;
            int row = idx >> 2, ci = idx & 3;
            *(uint4*)(As + row * 40 + ci * 8) =
                *(const uint4*)(Acat + (size_t)(m0 + row) * KCAT + k0 + ci * 8);
            *(uint4*)(Bs + row * 40 + ci * 8) =
                *(const uint4*)(Bcat + (size_t)(n0 + row) * KCAT + k0 + ci * 8);
        }
        __syncthreads();
#pragma unroll
        for (int ks = 0; ks < 2; ks++) {
            int kb = ks * 16;
            uint32_t af[4][4], bf[4][2];
#pragma unroll
            for (int mt = 0; mt < 4; mt++)
                ldsm4(af[mt], a_base + (uint32_t)(((wm * 64 + mt * 16 + a_r) * 40 + kb + a_c) * 2));
#pragma unroll
            for (int nt = 0; nt < 4; nt++)
                ldsm2(bf[nt], b_base + (uint32_t)(((wn * 32 + nt * 8 + b_r) * 40 + kb + b_c) * 2));
#pragma unroll
            for (int mt = 0; mt < 4; mt++)
#pragma unroll
                for (int nt = 0; nt < 4; nt++)
                    mma16816(acc[mt][nt], af[mt], bf[nt]);
        }
        __syncthreads();
    }
    int r = lane >> 2, cp = (lane & 3) * 2;
#pragma unroll
    for (int mt = 0; mt < 4; mt++) {
        int grow = m0 + wm * 64 + mt * 16 + r;
#pragma unroll
        for (int nt = 0; nt < 4; nt++) {
            int gcol = n0 + wn * 32 + nt * 8 + cp;
            float b0 = bias[gcol], b1 = bias[gcol + 1];
            float2 v0 = make_float2(acc[mt][nt][0] + b0, acc[mt][nt][1] + b1);
            float2 v1 = make_float2(acc[mt][nt][2] + b0, acc[mt][nt][3] + b1);
            *(float2*)(out + (size_t)grow * VOC + gcol) = v0;
            *(float2*)(out + (size_t)(grow + 8) * VOC + gcol) = v1;
        }
    }
}

// ---------------- scan (v2: 512 threads, fused M pass, parallel top8) ----------------
__device__ __forceinline__ void top8_extract(float a0, float a1, float* out, int lane) {
#pragma unroll
    for (int it = 0; it < 8; it++) {
        float m = fmaxf(a0, a1);
#pragma unroll
        for (int of = 16; of; of >>= 1) m = fmaxf(m, __shfl_xor_sync(0xffffffffu, m, of));
        unsigned b0 = __ballot_sync(0xffffffffu, a0 == m);
        if (b0) {
            if (lane == (__ffs(b0) - 1)) a0 = -3.4e38f;
        } else {
            unsigned b1 = __ballot_sync(0xffffffffu, a1 == m);
            if (lane == (__ffs(b1) - 1)) a1 = -3.4e38f;
        }
        if (lane == 0) out[it] = m;
    }
}

// floats: M 16896 | Wif 16512 | rv 128 | ifc 132 | Sr 512 | Sw 512 | candr 64 |
//         candw 64 | redr 8 | redw 8 | sumr 17 | sumw 17 | er 32 | pscr 512
#define SMEM_SCAN ((16896 + 16512 + 128 + 132 + 512 + 512 + 64 + 64 + 8 + 8 + 17 + 17 + 32 + 512) * 4)

__global__ __launch_bounds__(512) void scan_k(const float* __restrict__ ifh,
                                              const float* __restrict__ Wif_g,
                                              const float* __restrict__ br_p,
                                              const float* __restrict__ bw_p,
                                              float* __restrict__ rvh,
                                              int* __restrict__ flg) {
    int b = blockIdx.x >> 2, h = blockIdx.x & 3;
    int tid = threadIdx.x, lane = tid & 31, wid = tid >> 5;
    extern __shared__ float sm[];
    float* M     = sm;            // 512*33
    float* Wif   = M + 16896;     // 128*129
    float* rv    = Wif + 16512;   // 128
    float* ifc   = rv + 128;      // 132
    float* Sr    = ifc + 132;     // 512
    float* Sw    = Sr + 512;      // 512
    float* candr = Sw + 512;      // 64
    float* candw = candr + 64;    // 64
    float* redr  = candw + 64;    // 8
    float* redw  = redr + 8;      // 8
    float* sumr  = redw + 8;      // 17
    float* sumw  = sumr + 17;     // 17
    float* er    = sumw + 17;     // 32
    float* pscr  = er + 32;       // 512

    for (int i = tid; i < 16896; i += 512) M[i] = 0.f;
    for (int i = tid; i < 16512; i += 512) {
        int d = i / 129, j = i - d * 129;
        Wif[i] = Wif_g[(256 + d) * IFW + h * 129 + j];
    }
    float xr = br_p[0], xw = bw_p[0];
    float beta_r = fminf(fmaxf(xr > 20.f ? xr : log1pf(expf(xr)), 1.f), 20.f);
    float beta_w = fminf(fmaxf(xw > 20.f ? xw : log1pf(expf(xw)), 1.f), 20.f);
    __syncthreads();

    const int fb = b * 4;
    for (int t = 0; t < 128; t++) {
        if (t > 0) {
            if (tid < 4) {
                volatile int* vf = (volatile int*)(flg + fb + tid);
                while (*vf < t) {}
                __threadfence();
            }
            __syncthreads();
        }
        if (tid < 128) rv[tid] = rvh[(b * 129 + t) * 128 + tid];
        __syncthreads();

        // GEMV: ifc[j] = ifh_row[j] + sum_d rv[d] * Wif[d*129+j]; 2 threads/output
        {
            float acc = 0.f;
            int j = tid >> 1, half = tid & 1;
            if (tid < 258) {
                const float* wcol = Wif + j + half * (64 * 129);
                const float* rvp = rv + half * 64;
#pragma unroll 16
                for (int i = 0; i < 64; i++)
                    acc += rvp[i] * wcol[i * 129];
            }
            acc += __shfl_xor_sync(0xffffffffu, acc, 1);
            if (tid < 258 && half == 0)
                ifc[j] = acc + ifh[(b * 128 + t) * IFW + h * 129 + j];
        }
        __syncthreads();

        // scores: 1 slot per thread; keys broadcast via shfl
        {
            int s = tid;
            float rkv = ifc[lane], wkv = ifc[32 + lane];
            float sr = 0.f, sw = 0.f;
            const float* mrow = M + s * 33;
#pragma unroll 8
            for (int d = 0; d < 32; d++) {
                float m = mrow[d];
                sr += __shfl_sync(0xffffffffu, rkv, d) * m;
                sw += __shfl_sync(0xffffffffu, wkv, d) * m;
            }
            Sr[s] = sr * beta_r;
            Sw[s] = sw * beta_w;
            if (tid < 32) er[tid] = sigmoidf_(ifc[96 + tid]);
        }
        __syncthreads();

        // top8 level 1: warps 0-7 on Sr, warps 8-15 on Sw (concurrent)
        {
            int side = wid >> 3, w8 = wid & 7;
            float* S = side ? Sw : Sr;
            float* cnd = side ? candw : candr;
            top8_extract(S[w8 * 64 + lane], S[w8 * 64 + 32 + lane], cnd + w8 * 8, lane);
        }
        __syncthreads();
        if (wid == 0)      top8_extract(candr[lane], candr[32 + lane], redr, lane);
        else if (wid == 8) top8_extract(candw[lane], candw[32 + lane], redw, lane);
        __syncthreads();

        // exp (both sides) + per-warp partial sums
        {
            float mxr = redr[0], thr = redr[7];
            float mxw = redw[0], thw = redw[7];
            float vr = Sr[tid], vw = Sw[tid];
            float e_r = (vr >= thr) ? expf(vr - mxr) : 0.f;
            float e_w = (vw >= thw) ? expf(vw - mxw) : 0.f;
            Sr[tid] = e_r;
            Sw[tid] = e_w;
            float a = e_r, c = e_w;
#pragma unroll
            for (int of = 16; of; of >>= 1) {
                a += __shfl_xor_sync(0xffffffffu, a, of);
                c += __shfl_xor_sync(0xffffffffu, c, of);
            }
            if (lane == 0) { sumr[wid] = a; sumw[wid] = c; }
        }
        __syncthreads();
        if (tid == 0) {
            float s = 0.f;
#pragma unroll
            for (int i = 0; i < 16; i++) s += sumr[i];
            sumr[16] = s;
        } else if (tid == 32) {
            float s = 0.f;
#pragma unroll
            for (int i = 0; i < 16; i++) s += sumw[i];
            sumw[16] = s;
        }
        __syncthreads();

        // fused M pass: read-weighted reduction + erase/add update, one sweep
        {
            float inv_r = 1.f / sumr[16], inv_w = 1.f / sumw[16];
            float ag = sigmoidf_(ifc[128]);
            float er_d = er[lane], wv_d = ifc[64 + lane];
            float srv = Sr[wid * 32 + lane], swv = Sw[wid * 32 + lane];
            float pr = 0.f;
            float* mbase = M + (wid * 32) * 33 + lane;
#pragma unroll 4
            for (int i = 0; i < 32; i++) {
                float e_r = __shfl_sync(0xffffffffu, srv, i);
                float e_w = __shfl_sync(0xffffffffu, swv, i);
                float m = mbase[i * 33];
                pr += e_r * m;
                float a = e_w * inv_w;
                mbase[i * 33] = m * (1.f - a * er_d) + ag * a * wv_d;
            }
            pscr[wid * 32 + lane] = pr * inv_r;
        }
        __syncthreads();

        if (tid < 32) {
            float r = 0.f;
#pragma unroll
            for (int w = 0; w < 16; w++) r += pscr[w * 32 + tid];
            rvh[(b * 129 + t + 1) * 128 + h * 32 + tid] = rv[h * 32 + tid] + r;
        }
        __threadfence();
        __syncthreads();
        if (tid == 0) atomicExch(&flg[fb + h], t + 1);
    }
}

// ---------------- host launch ----------------
extern "C" void kernel_launch(void* const* d_in, const int* in_sizes, int n_in,
                              void* d_out, int out_size) {
    const int*   ids  = (const int*)d_in[0];
    const float* tok  = (const float*)d_in[1];
    const float* pos  = (const float*)d_in[2];
    const float* Wqkv = (const float*)d_in[3];
    const float* Wo   = (const float*)d_in[4];
    const float* l1g  = (const float*)d_in[5];
    const float* l1b  = (const float*)d_in[6];
    const float* l2g  = (const float*)d_in[7];
    const float* l2b  = (const float*)d_in[8];
    const float* W1   = (const float*)d_in[9];
    const float* b1   = (const float*)d_in[10];
    const float* W2   = (const float*)d_in[11];
    const float* b2   = (const float*)d_in[12];
    const float* lfg  = (const float*)d_in[13];
    const float* lfb  = (const float*)d_in[14];
    const float* WL   = (const float*)d_in[15];
    const float* bL   = (const float*)d_in[16];
    const float* WI   = (const float*)d_in[17];
    const float* bI   = (const float*)d_in[18];
    const float* br   = (const float*)d_in[19];
    const float* bw   = (const float*)d_in[20];
    float* out = (float*)d_out;

    float *x, *h, *qkv, *o, *ff, *A, *ifh, *rvh;
    __nv_bfloat16 *Acat, *Bcat;
    int* flg;
    cudaGetSymbolAddress((void**)&x, g_x);
    cudaGetSymbolAddress((void**)&h, g_h);
    cudaGetSymbolAddress((void**)&qkv, g_qkv);
    cudaGetSymbolAddress((void**)&o, g_o);
    cudaGetSymbolAddress((void**)&ff, g_ff);
    cudaGetSymbolAddress((void**)&A, g_A);
    cudaGetSymbolAddress((void**)&ifh, g_ifh);
    cudaGetSymbolAddress((void**)&rvh, g_rvh);
    cudaGetSymbolAddress((void**)&Acat, g_Acat);
    cudaGetSymbolAddress((void**)&Bcat, g_Bcat);
    cudaGetSymbolAddress((void**)&flg, g_flags);

    cudaFuncSetAttribute(scan_k, cudaFuncAttributeMaxDynamicSharedMemorySize, SMEM_SCAN);

    clear_k<<<259, 256>>>(rvh, flg);
    embed_k<<<512, 256>>>(ids, tok, pos, x);
    prepB_k<<<dim3(1000, 12), 256>>>(WL, Bcat);

    for (int l = 0; l < 2; l++) {
        ln_k<<<64, 256>>>(x, l1g + l * 256, l1b + l * 256, h, 256);
        gemm_k<64, 64, 4, 4, false, false, false, false>
            <<<dim3(12, 8), 256>>>(h, Wqkv + l * 256 * 768, nullptr, nullptr, qkv,
                                   512, 768, 256, 256, 768, 768);
        attn_k<<<32, 128>>>(qkv, o);
        gemm_k<64, 64, 4, 4, false, false, true, false>
            <<<dim3(4, 8), 256>>>(o, Wo + l * 256 * 256, nullptr, x, x,
                                  512, 256, 256, 256, 256, 256);
        ln_k<<<64, 256>>>(x, l2g + l * 256, l2b + l * 256, h, 256);
        gemm_k<64, 64, 4, 4, true, true, false, false>
            <<<dim3(16, 8), 256>>>(h, W1 + l * 256 * 1024, b1 + l * 1024, nullptr, ff,
                                   512, 1024, 256, 256, 1024, 1024);
        gemm_k<64, 64, 4, 4, true, false, true, false>
            <<<dim3(4, 8), 256>>>(ff, W2 + l * 1024 * 256, b2 + l * 256, x, x,
                                  512, 256, 1024, 1024, 256, 256);
    }
    ln_k<<<64, 256>>>(x, lfg, lfb, A, 384);
    gemm_k<64, 64, 4, 4, true, false, false, true>
        <<<dim3(9, 8), 256>>>(A, WI, bI, nullptr, ifh, 512, 516, 256, 384, 516, 516);
    scan_k<<<16, 512, SMEM_SCAN>>>(ifh, WI, br, bw, rvh, flg);
    copy_rv_k<<<256, 256>>>(rvh, A);
    prepA_k<<<768, 256>>>(A, Acat);
    logits_mma_k<<<dim3(250, 4), 256>>>(Acat, Bcat, bL, out);
}